// round 4
// baseline (speedup 1.0000x reference)
#include <cuda_runtime.h>
#include <cuda_bf16.h>

// ---------------------------------------------------------------------------
// Single fused kernel with per-hidden-value producer/consumer flags.
//   Blocks 0..69   : producer i — full dot(inputs[row_i], W1) + scalar relu
//                    chain -> g_h[i], then release-store g_flag[i]=1.
//   Blocks 70..473 : consumers — prefetch W3b/b3b/W4b/b4b operands, then
//                    acquire-poll ONLY the flag for their own h index, emit
//                    4 output floats each.
// Deadlock-free: 474 blocks of 256 threads all fit in wave 1 (>=592 capacity).
// ---------------------------------------------------------------------------

#define NROW   70
#define NCONS  404
#define NBLK   (NROW + NCONS)
#define SEG3_END  409600
#define ZERO_END  409664
#define OUT_TOTAL 412742

__device__ float g_h[NROW];
__device__ int   g_flag[NROW];   // zero-init at load; reset by last block each run
__device__ int   g_done;

__device__ __forceinline__ float frelu(float v) { return fmaxf(v, 0.f); }

__device__ __forceinline__ void wait_flag(const int* p) {
    int f;
    while (true) {
        asm volatile("ld.acquire.gpu.b32 %0, [%1];" : "=r"(f) : "l"(p) : "memory");
        if (f) return;
        __nanosleep(32);
    }
}

__global__ __launch_bounds__(256, 4)
void fused_kernel(const float* __restrict__ inp,
                  const float* __restrict__ W1,
                  const float* __restrict__ b1,
                  const float* __restrict__ W2,
                  const float* __restrict__ b2,
                  const float* __restrict__ W3a,
                  const float* __restrict__ b3a,
                  const float* __restrict__ W3b,
                  const float* __restrict__ b3b,
                  const float* __restrict__ W4a,
                  const float* __restrict__ b4a,
                  const float* __restrict__ W4b,
                  const float* __restrict__ b4b,
                  float* __restrict__ out) {
    const int bid = blockIdx.x;
    const int tid = threadIdx.x;

    if (bid < NROW) {
        // ================= PRODUCER =================
        const int i = bid;
        const int row = (i < 64) ? (i * 64) : (((i - 64) * 2048) / 3);

        // Prefetch the tiny scalar-chain operands first (overlap with dot).
        float c_b1 = 0.f, c_W2 = 0.f, c_b2 = 0.f, c_wa = 0.f, c_ba = 0.f;
        if (tid == 0) {
            int col;
            if (i < 64) col = 1;
            else {
                int m = (i - 64) % 3;            // 65, 69, 67 repeating
                col = (m == 0) ? 65 : (m == 1) ? 69 : 67;
            }
            c_b1 = __ldg(&b1[0]);
            c_W2 = __ldg(&W2[col]);
            c_b2 = __ldg(&b2[col]);
            c_wa = (i < 64) ? __ldg(&W3a[0]) : __ldg(&W4a[0]);
            c_ba = (i < 64) ? __ldg(&b3a[0]) : __ldg(&b4a[0]);
        }

        // dot over 1600 float4: 6 full strides + partial (tid < 64).
        const float4* __restrict__ ip = (const float4*)(inp + (size_t)row * 6400);
        const float4* __restrict__ wp = (const float4*)W1;

        float4 a[7], w[7];
        #pragma unroll
        for (int k = 0; k < 6; k++) {
            a[k] = ip[tid + 256 * k];
            w[k] = wp[tid + 256 * k];
        }
        if (tid < 64) { a[6] = ip[tid + 1536]; w[6] = wp[tid + 1536]; }
        else          { a[6] = make_float4(0,0,0,0); w[6] = make_float4(0,0,0,0); }

        float sum = 0.f;
        #pragma unroll
        for (int k = 0; k < 7; k++)
            sum += a[k].x * w[k].x + a[k].y * w[k].y + a[k].z * w[k].z + a[k].w * w[k].w;

        #pragma unroll
        for (int off = 16; off; off >>= 1)
            sum += __shfl_down_sync(0xffffffffu, sum, off);

        __shared__ float ws[8];
        if ((tid & 31) == 0) ws[tid >> 5] = sum;
        __syncthreads();
        if (tid == 0) {
            float t = 0.f;
            #pragma unroll
            for (int q = 0; q < 8; q++) t += ws[q];
            float s = frelu(t + c_b1);
            float x = frelu(fmaf(s, c_W2, c_b2));
            float h = frelu(fmaf(x, c_wa, c_ba));
            // Publish: data, fence, release flag.
            asm volatile("st.global.cg.f32 [%0], %1;" :: "l"(&g_h[i]), "f"(h) : "memory");
            __threadfence();
            asm volatile("st.release.gpu.b32 [%0], %1;" :: "l"(&g_flag[i]), "r"(1) : "memory");
        }
    } else {
        // ================= CONSUMER =================
        const int cid = bid - NROW;
        const int o4  = cid * 256 + tid;
        const int o   = o4 * 4;

        float wA0 = 0.f, wA1 = 0.f, wA2 = 0.f, wA3 = 0.f;
        float bA0 = 0.f, bA1 = 0.f, bA2 = 0.f, bA3 = 0.f;
        int   hIdx = -1;
        int   h0 = -1, h1 = -1, h2 = -1, h3 = -1;

        const bool seg3 = (o < SEG3_END);
        if (seg3) {
            int q4 = o4 % 1280;          // float4 index within one 5120-float tile
            hIdx   = q4 / 20;            // 20 float4 per hidden scalar (80 floats)
            int k4 = q4 % 20;
            float4 wq = ((const float4*)W3b)[k4];
            float4 bq = ((const float4*)b3b)[k4];
            wA0 = wq.x; wA1 = wq.y; wA2 = wq.z; wA3 = wq.w;
            bA0 = bq.x; bA1 = bq.y; bA2 = bq.z; bA3 = bq.w;
        } else if (o < OUT_TOTAL) {
            #pragma unroll
            for (int l = 0; l < 4; l++) {
                int e = o + l;
                float wv = 0.f, bv = 0.f; int hv = -1;
                if (e >= ZERO_END && e < OUT_TOTAL) {
                    int p  = e - ZERO_END;
                    int i4 = p / 513;
                    int k  = p - i4 * 513;
                    wv = W4b[k]; bv = b4b[k]; hv = 64 + i4;
                }
                if (l == 0) { wA0 = wv; bA0 = bv; h0 = hv; }
                if (l == 1) { wA1 = wv; bA1 = bv; h1 = hv; }
                if (l == 2) { wA2 = wv; bA2 = bv; h2 = hv; }
                if (l == 3) { wA3 = wv; bA3 = bv; h3 = hv; }
            }
        }

        if (seg3) {
            wait_flag(&g_flag[hIdx]);
            float h = __ldcg(&g_h[hIdx]);
            float4 r;
            r.x = frelu(fmaf(h, wA0, bA0));
            r.y = frelu(fmaf(h, wA1, bA1));
            r.z = frelu(fmaf(h, wA2, bA2));
            r.w = frelu(fmaf(h, wA3, bA3));
            *(float4*)(out + o) = r;
        } else if (o < OUT_TOTAL) {
            if (o + 0 < OUT_TOTAL) {
                float v = 0.f;
                if (h0 >= 0) { wait_flag(&g_flag[h0]); v = frelu(fmaf(__ldcg(&g_h[h0]), wA0, bA0)); }
                out[o + 0] = v;
            }
            if (o + 1 < OUT_TOTAL) {
                float v = 0.f;
                if (h1 >= 0) { wait_flag(&g_flag[h1]); v = frelu(fmaf(__ldcg(&g_h[h1]), wA1, bA1)); }
                out[o + 1] = v;
            }
            if (o + 2 < OUT_TOTAL) {
                float v = 0.f;
                if (h2 >= 0) { wait_flag(&g_flag[h2]); v = frelu(fmaf(__ldcg(&g_h[h2]), wA2, bA2)); }
                out[o + 2] = v;
            }
            if (o + 3 < OUT_TOTAL) {
                float v = 0.f;
                if (h3 >= 0) { wait_flag(&g_flag[h3]); v = frelu(fmaf(__ldcg(&g_h[h3]), wA3, bA3)); }
                out[o + 3] = v;
            }
        }
    }

    // --- Reset for next graph replay: last finishing block clears flags. ---
    __syncthreads();
    if (tid == 0) {
        int old = atomicAdd(&g_done, 1);
        if (old == NBLK - 1) {
            #pragma unroll
            for (int q = 0; q < NROW; q++) g_flag[q] = 0;
            g_done = 0;
            __threadfence();
        }
    }
}

extern "C" void kernel_launch(void* const* d_in, const int* in_sizes, int n_in,
                              void* d_out, int out_size) {
    const float* inp = (const float*)d_in[0];
    const float* W1  = (const float*)d_in[1];
    const float* b1  = (const float*)d_in[2];
    const float* W2  = (const float*)d_in[3];
    const float* b2  = (const float*)d_in[4];
    const float* W3a = (const float*)d_in[5];
    const float* b3a = (const float*)d_in[6];
    const float* W3b = (const float*)d_in[7];
    const float* b3b = (const float*)d_in[8];
    const float* W4a = (const float*)d_in[9];
    const float* b4a = (const float*)d_in[10];
    const float* W4b = (const float*)d_in[11];
    const float* b4b = (const float*)d_in[12];
    float* out = (float*)d_out;

    fused_kernel<<<NBLK, 256>>>(inp, W1, b1, W2, b2, W3a, b3a,
                                W3b, b3b, W4a, b4a, W4b, b4b, out);
}

// round 5
// speedup vs baseline: 1.7316x; 1.7316x over previous
#include <cuda_runtime.h>
#include <cuda_bf16.h>

// ---------------------------------------------------------------------------
// PDL two-kernel structure (R3 skeleton, improved):
//   Kernel 1 (70 blocks x 512): full dot(inputs[row_i], W1) + scalar relu
//     chain -> g_h[i]. Blocks 64..69 also write the sel4 tail (513 floats
//     each); block 0 writes the 64-zero band.
//   Kernel 2 (PDL secondary, 80 blocks x 256): block t writes repetition
//     tile t of seg3 (5120 floats). Prefetches W3b/b3b (20 float4 each)
//     before the grid sync; post-sync work = g_h broadcast + stores only.
// seg3 fact used: out[t*5120 + q] is identical for all t (tile(sel3, 80)).
// ---------------------------------------------------------------------------

#define NROW   70
#define SEG3_END  409600
#define ZERO_END  409664
#define OUT_TOTAL 412742

__device__ float g_h[NROW];

__device__ __forceinline__ float frelu(float v) { return fmaxf(v, 0.f); }

// ---------------------------------------------------------------------------
// Kernel 1: producer. Block i -> hidden scalar i (+ tail/zero writes).
// ---------------------------------------------------------------------------
__global__ __launch_bounds__(512)
void producer_kernel(const float* __restrict__ inp,
                     const float* __restrict__ W1,
                     const float* __restrict__ b1,
                     const float* __restrict__ W2,
                     const float* __restrict__ b2,
                     const float* __restrict__ W3a,
                     const float* __restrict__ b3a,
                     const float* __restrict__ W4a,
                     const float* __restrict__ b4a,
                     const float* __restrict__ W4b,
                     const float* __restrict__ b4b,
                     float* __restrict__ out) {
    cudaTriggerProgrammaticLaunchCompletion();

    const int i   = blockIdx.x;
    const int tid = threadIdx.x;
    const int row = (i < 64) ? (i * 64) : (((i - 64) * 2048) / 3);

    // Scalar-chain operands (tid 0 only) — issued before the big dot so the
    // latency overlaps it.
    float c_b1 = 0.f, c_W2 = 0.f, c_b2 = 0.f, c_wa = 0.f, c_ba = 0.f;
    if (tid == 0) {
        int col;
        if (i < 64) col = 1;
        else {
            int m = (i - 64) % 3;                // 65, 69, 67 repeating
            col = (m == 0) ? 65 : (m == 1) ? 69 : 67;
        }
        c_b1 = __ldg(&b1[0]);
        c_W2 = __ldg(&W2[col]);
        c_b2 = __ldg(&b2[col]);
        c_wa = (i < 64) ? __ldg(&W3a[0]) : __ldg(&W4a[0]);
        c_ba = (i < 64) ? __ldg(&b3a[0]) : __ldg(&b4a[0]);
    }

    // Tail operands for blocks 64..69 (independent of the dot).
    float twv = 0.f, tbv = 0.f;
    if (i >= 64 && tid < 513) {
        twv = __ldg(&W4b[tid]);
        tbv = __ldg(&b4b[tid]);
    }

    // dot over 1600 float4: strides of 512 -> 3 full + partial (tid < 64).
    const float4* __restrict__ ip = (const float4*)(inp + (size_t)row * 6400);
    const float4* __restrict__ wp = (const float4*)W1;

    float4 a0 = ip[tid];        float4 w0 = wp[tid];
    float4 a1 = ip[tid + 512];  float4 w1 = wp[tid + 512];
    float4 a2 = ip[tid + 1024]; float4 w2 = wp[tid + 1024];
    float4 a3, w3;
    if (tid < 64) { a3 = ip[tid + 1536]; w3 = wp[tid + 1536]; }
    else          { a3 = make_float4(0,0,0,0); w3 = make_float4(0,0,0,0); }

    float sum = a0.x*w0.x + a0.y*w0.y + a0.z*w0.z + a0.w*w0.w
              + a1.x*w1.x + a1.y*w1.y + a1.z*w1.z + a1.w*w1.w
              + a2.x*w2.x + a2.y*w2.y + a2.z*w2.z + a2.w*w2.w
              + a3.x*w3.x + a3.y*w3.y + a3.z*w3.z + a3.w*w3.w;

    #pragma unroll
    for (int off = 16; off; off >>= 1)
        sum += __shfl_down_sync(0xffffffffu, sum, off);

    __shared__ float ws[16];
    __shared__ float hsh;
    if ((tid & 31) == 0) ws[tid >> 5] = sum;
    __syncthreads();

    if (tid == 0) {
        float t = 0.f;
        #pragma unroll
        for (int q = 0; q < 16; q++) t += ws[q];
        float s = frelu(t + c_b1);                 // layer 1
        float x = frelu(fmaf(s, c_W2, c_b2));      // layer 2 (one column)
        float h = frelu(fmaf(x, c_wa, c_ba));      // layer 3a/4a hidden
        g_h[i] = h;
        hsh = h;
    }

    // Zero band (block 0) — independent of h.
    if (i == 0 && tid < 64) out[SEG3_END + tid] = 0.f;

    // sel4 tail: blocks 64..69 write their 513 floats.
    if (i >= 64) {
        __syncthreads();
        float h = hsh;
        if (tid < 513) {
            out[ZERO_END + (i - 64) * 513 + tid] = frelu(fmaf(h, twv, tbv));
        }
        if (tid == 0) {
            out[ZERO_END + (i - 64) * 513 + 512] = frelu(fmaf(h, __ldg(&W4b[512]), __ldg(&b4b[512])));
        }
    }
}

// ---------------------------------------------------------------------------
// Kernel 2 (PDL secondary): block t writes seg3 repetition tile t.
// Each thread handles 5 unique float4 groups (1280 groups per tile).
// ---------------------------------------------------------------------------
__global__ __launch_bounds__(256)
void seg3_kernel(const float* __restrict__ W3b,
                 const float* __restrict__ b3b,
                 float* __restrict__ out) {
    const int t   = blockIdx.x;      // repetition 0..79
    const int tid = threadIdx.x;

    // Prefetch operands (independent of kernel 1).
    float4 w[5], b[5];
    int hidx[5];
    #pragma unroll
    for (int j = 0; j < 5; j++) {
        int q4 = tid + 256 * j;      // unique group 0..1279
        hidx[j] = q4 / 20;           // 20 float4 per hidden scalar
        int k4  = q4 % 20;
        w[j] = ((const float4*)W3b)[k4];
        b[j] = ((const float4*)b3b)[k4];
    }

    cudaGridDependencySynchronize();

    float4* __restrict__ dst = ((float4*)out) + t * 1280;
    #pragma unroll
    for (int j = 0; j < 5; j++) {
        float h = __ldcg(&g_h[hidx[j]]);
        float4 r;
        r.x = frelu(fmaf(h, w[j].x, b[j].x));
        r.y = frelu(fmaf(h, w[j].y, b[j].y));
        r.z = frelu(fmaf(h, w[j].z, b[j].z));
        r.w = frelu(fmaf(h, w[j].w, b[j].w));
        dst[tid + 256 * j] = r;
    }
}

extern "C" void kernel_launch(void* const* d_in, const int* in_sizes, int n_in,
                              void* d_out, int out_size) {
    const float* inp = (const float*)d_in[0];
    const float* W1  = (const float*)d_in[1];
    const float* b1  = (const float*)d_in[2];
    const float* W2  = (const float*)d_in[3];
    const float* b2  = (const float*)d_in[4];
    const float* W3a = (const float*)d_in[5];
    const float* b3a = (const float*)d_in[6];
    const float* W3b = (const float*)d_in[7];
    const float* b3b = (const float*)d_in[8];
    const float* W4a = (const float*)d_in[9];
    const float* b4a = (const float*)d_in[10];
    const float* W4b = (const float*)d_in[11];
    const float* b4b = (const float*)d_in[12];
    float* out = (float*)d_out;

    producer_kernel<<<NROW, 512>>>(inp, W1, b1, W2, b2, W3a, b3a,
                                   W4a, b4a, W4b, b4b, out);

    cudaLaunchConfig_t cfg = {};
    cfg.gridDim  = dim3(80);
    cfg.blockDim = dim3(256);
    cfg.dynamicSmemBytes = 0;
    cfg.stream = 0;
    cudaLaunchAttribute attr[1];
    attr[0].id = cudaLaunchAttributeProgrammaticStreamSerialization;
    attr[0].val.programmaticStreamSerializationAllowed = 1;
    cfg.attrs = attr;
    cfg.numAttrs = 1;
    cudaLaunchKernelEx(&cfg, seg3_kernel, W3b, b3b, out);
}

// round 6
// speedup vs baseline: 2.2644x; 1.3077x over previous
#include <cuda_runtime.h>
#include <cuda_bf16.h>

// ---------------------------------------------------------------------------
// SINGLE kernel, zero synchronization. Partition by hidden scalar:
//   block i (0..63):  h3[i] = chain(dot(inputs[i*64], W1)); writes its 80-float
//                     row relu(h*W3b+b3b) into ALL 80 seg3 repetition tiles
//                     (out[t*5120 + i*80 + k], 6400 floats).
//   block i (64..69): h4 = chain(dot(inputs[row], W1), cols 65/69/67); writes
//                     its 513-float sel4 row.
//   block 0 also writes the 64-zero band.
// No cross-block dependency exists, so no grid sync / PDL / flags needed.
// ---------------------------------------------------------------------------

#define NROW      70
#define SEG3_END  409600
#define ZERO_END  409664
#define OUT_TOTAL 412742

__device__ __forceinline__ float frelu(float v) { return fmaxf(v, 0.f); }

__global__ __launch_bounds__(512)
void hyper_kernel(const float* __restrict__ inp,
                  const float* __restrict__ W1,
                  const float* __restrict__ b1,
                  const float* __restrict__ W2,
                  const float* __restrict__ b2,
                  const float* __restrict__ W3a,
                  const float* __restrict__ b3a,
                  const float* __restrict__ W3b,
                  const float* __restrict__ b3b,
                  const float* __restrict__ W4a,
                  const float* __restrict__ b4a,
                  const float* __restrict__ W4b,
                  const float* __restrict__ b4b,
                  float* __restrict__ out) {
    const int i   = blockIdx.x;
    const int tid = threadIdx.x;
    const int row = (i < 64) ? (i * 64) : (((i - 64) * 2048) / 3);

    // ---- Prefetch small operands first; latency overlaps the big dot. ----
    float c_b1 = 0.f, c_W2 = 0.f, c_b2 = 0.f, c_wa = 0.f, c_ba = 0.f;
    if (tid == 0) {
        int col;
        if (i < 64) col = 1;
        else {
            int m = (i - 64) % 3;                 // 65, 69, 67 repeating
            col = (m == 0) ? 65 : (m == 1) ? 69 : 67;
        }
        c_b1 = __ldg(&b1[0]);
        c_W2 = __ldg(&W2[col]);
        c_b2 = __ldg(&b2[col]);
        c_wa = (i < 64) ? __ldg(&W3a[0]) : __ldg(&W4a[0]);
        c_ba = (i < 64) ? __ldg(&b3a[0]) : __ldg(&b4a[0]);
    }

    // Output-row operands.
    //   i < 64 : thread (tid<500) owns k4 = tid%20 -> W3b/b3b float4.
    //   i >= 64: thread tid owns W4b[tid], b4b[tid] (tid 0 also element 512).
    float4 wq = make_float4(0, 0, 0, 0), bq = make_float4(0, 0, 0, 0);
    float  twv = 0.f, tbv = 0.f, twv2 = 0.f, tbv2 = 0.f;
    const int k4 = tid % 20;
    const int tg = tid / 20;                      // 0..25
    if (i < 64) {
        if (tid < 500) {
            wq = ((const float4*)W3b)[k4];
            bq = ((const float4*)b3b)[k4];
        }
    } else {
        twv = __ldg(&W4b[tid]);
        tbv = __ldg(&b4b[tid]);
        if (tid == 0) { twv2 = __ldg(&W4b[512]); tbv2 = __ldg(&b4b[512]); }
    }

    // ---- dot(inputs[row], W1): 1600 float4, stride 512 -> 3 full + tail ----
    const float4* __restrict__ ip = (const float4*)(inp + (size_t)row * 6400);
    const float4* __restrict__ wp = (const float4*)W1;

    float4 a0 = ip[tid];        float4 w0 = wp[tid];
    float4 a1 = ip[tid + 512];  float4 w1 = wp[tid + 512];
    float4 a2 = ip[tid + 1024]; float4 w2 = wp[tid + 1024];
    float4 a3, w3;
    if (tid < 64) { a3 = ip[tid + 1536]; w3 = wp[tid + 1536]; }
    else          { a3 = make_float4(0,0,0,0); w3 = make_float4(0,0,0,0); }

    float sum = a0.x*w0.x + a0.y*w0.y + a0.z*w0.z + a0.w*w0.w
              + a1.x*w1.x + a1.y*w1.y + a1.z*w1.z + a1.w*w1.w
              + a2.x*w2.x + a2.y*w2.y + a2.z*w2.z + a2.w*w2.w
              + a3.x*w3.x + a3.y*w3.y + a3.z*w3.z + a3.w*w3.w;

    #pragma unroll
    for (int off = 16; off; off >>= 1)
        sum += __shfl_down_sync(0xffffffffu, sum, off);

    __shared__ float ws[16];
    __shared__ float hsh;
    if ((tid & 31) == 0) ws[tid >> 5] = sum;
    __syncthreads();

    if (tid == 0) {
        float t = 0.f;
        #pragma unroll
        for (int q = 0; q < 16; q++) t += ws[q];
        float s = frelu(t + c_b1);                 // layer 1
        float x = frelu(fmaf(s, c_W2, c_b2));      // layer 2 (one column)
        hsh = frelu(fmaf(x, c_wa, c_ba));          // layer 3a/4a hidden
    }

    // Zero band (block 0): independent of h.
    if (i == 0 && tid < 64) out[SEG3_END + tid] = 0.f;

    __syncthreads();
    const float h = hsh;

    if (i < 64) {
        // Row value for this thread's k4 (identical across all 80 tiles).
        if (tid < 500) {
            float4 r;
            r.x = frelu(fmaf(h, wq.x, bq.x));
            r.y = frelu(fmaf(h, wq.y, bq.y));
            r.z = frelu(fmaf(h, wq.z, bq.z));
            r.w = frelu(fmaf(h, wq.w, bq.w));
            // Store into tiles t = tg, tg+25, tg+50, tg+75 (guard t < 80).
            float4* __restrict__ base4 = ((float4*)out) + i * 20 + k4;
            #pragma unroll
            for (int rep = 0; rep < 4; rep++) {
                int t = tg + 25 * rep;
                if (t < 80) base4[t * 1280] = r;
            }
        }
    } else {
        const int obase = ZERO_END + (i - 64) * 513;
        out[obase + tid] = frelu(fmaf(h, twv, tbv));
        if (tid == 0) out[obase + 512] = frelu(fmaf(h, twv2, tbv2));
    }
}

extern "C" void kernel_launch(void* const* d_in, const int* in_sizes, int n_in,
                              void* d_out, int out_size) {
    const float* inp = (const float*)d_in[0];
    const float* W1  = (const float*)d_in[1];
    const float* b1  = (const float*)d_in[2];
    const float* W2  = (const float*)d_in[3];
    const float* b2  = (const float*)d_in[4];
    const float* W3a = (const float*)d_in[5];
    const float* b3a = (const float*)d_in[6];
    const float* W3b = (const float*)d_in[7];
    const float* b3b = (const float*)d_in[8];
    const float* W4a = (const float*)d_in[9];
    const float* b4a = (const float*)d_in[10];
    const float* W4b = (const float*)d_in[11];
    const float* b4b = (const float*)d_in[12];
    float* out = (float*)d_out;

    hyper_kernel<<<NROW, 512>>>(inp, W1, b1, W2, b2, W3a, b3a,
                                W3b, b3b, W4a, b4a, W4b, b4b, out);
}